// round 7
// baseline (speedup 1.0000x reference)
#include <cuda_runtime.h>
#include <cstdint>

// GeometricLoss via spatial grid: N=8192 2D points, k=5 NN (excl. self),
// mean of 16-ch L2 norms of output differences.
// R7: 64x64 uniform grid, counting-sort binning, per-query expanding-ring
// search (exact termination bound), exact key selection -> deterministic.

#define NPTS 8192
#define NCH 16
#define KNN 5
#define G 64
#define NCELL (G * G)
typedef unsigned long long ull;
#define SENT 0x7F800000FFFFFFFFULL  // (inf_bits<<32) | 0xFFFFFFFF

__device__ float2 g_pxy[NPTS];      // binned points
__device__ int g_pid[NPTS];         // original index of binned point
__device__ int g_cellof[NPTS];      // cell of original point i
__device__ int g_count[NCELL];
__device__ int g_start[NCELL];
__device__ int g_cursor[NCELL];
__device__ float g_partial[NPTS];
__device__ unsigned g_ticket;
__device__ float g_minx, g_miny, g_invw, g_invh, g_cwmin;

// ---------------- K1: zero + bbox + grid params (1 CTA) ----------------
__global__ __launch_bounds__(1024)
void init_kernel(const float2* __restrict__ pts) {
    const int tid = threadIdx.x;
    for (int c = tid; c < NCELL; c += 1024) g_count[c] = 0;
    if (tid == 0) g_ticket = 0;

    float mnx = 1e30f, mxx = -1e30f, mny = 1e30f, mxy = -1e30f;
    for (int j = tid; j < NPTS; j += 1024) {
        float2 p = pts[j];
        mnx = fminf(mnx, p.x); mxx = fmaxf(mxx, p.x);
        mny = fminf(mny, p.y); mxy = fmaxf(mxy, p.y);
    }
#pragma unroll
    for (int off = 16; off > 0; off >>= 1) {
        mnx = fminf(mnx, __shfl_xor_sync(0xFFFFFFFFu, mnx, off));
        mxx = fmaxf(mxx, __shfl_xor_sync(0xFFFFFFFFu, mxx, off));
        mny = fminf(mny, __shfl_xor_sync(0xFFFFFFFFu, mny, off));
        mxy = fmaxf(mxy, __shfl_xor_sync(0xFFFFFFFFu, mxy, off));
    }
    __shared__ float s0[32], s1[32], s2[32], s3[32];
    int warp = tid >> 5, lane = tid & 31;
    if (lane == 0) { s0[warp] = mnx; s1[warp] = mxx; s2[warp] = mny; s3[warp] = mxy; }
    __syncthreads();
    if (tid == 0) {
        for (int w = 1; w < 32; w++) {
            mnx = fminf(s0[0], s0[w]); s0[0] = mnx;
            mxx = fmaxf(s1[0], s1[w]); s1[0] = mxx;
            mny = fminf(s2[0], s2[w]); s2[0] = mny;
            mxy = fmaxf(s3[0], s3[w]); s3[0] = mxy;
        }
        mnx = s0[0]; mxx = s1[0]; mny = s2[0]; mxy = s3[0];
        float w = mxx - mnx, h = mxy - mny;
        g_minx = mnx; g_miny = mny;
        g_invw = (w > 0.0f) ? (float)G / w : 0.0f;
        g_invh = (h > 0.0f) ? (float)G / h : 0.0f;
        float cw = w / (float)G, ch = h / (float)G;
        g_cwmin = fminf(cw, ch);
    }
}

__device__ __forceinline__ int cell_of(float2 p) {
    int cx = (int)((p.x - g_minx) * g_invw);
    int cy = (int)((p.y - g_miny) * g_invh);
    cx = min(max(cx, 0), G - 1);
    cy = min(max(cy, 0), G - 1);
    return cy * G + cx;
}

// ---------------- K2: bin counting ----------------
__global__ __launch_bounds__(256)
void bin_kernel(const float2* __restrict__ pts) {
    int i = blockIdx.x * 256 + threadIdx.x;
    int c = cell_of(pts[i]);
    g_cellof[i] = c;
    atomicAdd(&g_count[c], 1);
}

// ---------------- K3: prefix scan over 4096 counts (1 CTA) ----------------
__global__ __launch_bounds__(1024)
void prefix_kernel() {
    __shared__ int tsum[1024];
    const int tid = threadIdx.x;
    const int base = tid * 4;
    int v[4];
    int s = 0;
#pragma unroll
    for (int i = 0; i < 4; i++) { v[i] = s; s += g_count[base + i]; }
    tsum[tid] = s;
    __syncthreads();
    for (int off = 1; off < 1024; off <<= 1) {
        int x = tsum[tid];
        int y = (tid >= off) ? tsum[tid - off] : 0;
        __syncthreads();
        tsum[tid] = x + y;
        __syncthreads();
    }
    int prev = (tid > 0) ? tsum[tid - 1] : 0;
#pragma unroll
    for (int i = 0; i < 4; i++) {
        int st = prev + v[i];
        g_start[base + i] = st;
        g_cursor[base + i] = st;
    }
}

// ---------------- K4: scatter ----------------
__global__ __launch_bounds__(256)
void scatter_kernel(const float2* __restrict__ pts) {
    int i = blockIdx.x * 256 + threadIdx.x;
    int c = g_cellof[i];
    int slot = atomicAdd(&g_cursor[c], 1);
    g_pxy[slot] = pts[i];
    g_pid[slot] = i;
}

// ---------------- K5: per-query ring search + epilogue + reduction ----------
#define K5_TPB 128
#define K5_NBLK (NPTS / K5_TPB)   // 64

__device__ __forceinline__ void scan_cell(int cx, int cy, float qx, float qy,
                                          ull* b, float& th) {
    int c = cy * G + cx;
    int s = g_start[c];
    int e = s + g_count[c];
    for (int j = s; j < e; j++) {
        float2 p = g_pxy[j];
        float dx = qx - p.x;
        float dy = qy - p.y;
        float d2 = fmaf(dx, dx, dy * dy);
        if (d2 <= th) {  // <= : boundary ties resolved exactly by key below
            ull key = ((ull)__float_as_uint(d2) << 32) | (unsigned)g_pid[j];
            if (key < b[5]) {
                b[5] = key;
#pragma unroll
                for (int t = 5; t > 0; t--) {
                    if (b[t] < b[t - 1]) { ull tmp = b[t]; b[t] = b[t - 1]; b[t - 1] = tmp; }
                }
                th = __uint_as_float((unsigned)(b[5] >> 32));
            }
        }
    }
}

__global__ __launch_bounds__(K5_TPB)
void search_kernel(const float* __restrict__ outputs,
                   const float2* __restrict__ pts,
                   float* __restrict__ out) {
    const int i = blockIdx.x * K5_TPB + threadIdx.x;
    const float2 q = pts[i];
    const int qc = g_cellof[i];
    const int cx = qc % G, cy = qc / G;
    const float cwmin = g_cwmin;

    ull b[6];
#pragma unroll
    for (int t = 0; t < 6; t++) b[t] = SENT;
    float th = __int_as_float(0x7F800000);

    for (int d = 0; d < G; d++) {
        if (d >= 1) {
            // unscanned points lie in rings >= d -> distance >= (d-1)*cwmin
            float bnd = (float)(d - 1) * cwmin;
            if (th <= bnd * bnd) break;
        }
        if (d == 0) {
            scan_cell(cx, cy, q.x, q.y, b, th);
        } else {
            int x0 = cx - d, x1 = cx + d, y0 = cy - d, y1 = cy + d;
            int xa = max(x0, 0), xb = min(x1, G - 1);
            for (int x = xa; x <= xb; x++) {
                if (y0 >= 0)     scan_cell(x, y0, q.x, q.y, b, th);
                if (y1 <= G - 1) scan_cell(x, y1, q.x, q.y, b, th);
            }
            int ya = max(y0 + 1, 0), yb = min(y1 - 1, G - 1);
            for (int y = ya; y <= yb; y++) {
                if (x0 >= 0)     scan_cell(x0, y, q.x, q.y, b, th);
                if (x1 <= G - 1) scan_cell(x1, y, q.x, q.y, b, th);
            }
        }
    }

    // epilogue: ranks 1..5 are the neighbors (rank 0 = min key = self slot)
    float ssum = 0.0f;
    const float4* oq = (const float4*)(outputs + (size_t)i * NCH);
    float4 a0 = oq[0], a1 = oq[1], a2 = oq[2], a3 = oq[3];
#pragma unroll
    for (int r = 1; r <= KNN; r++) {
        int nb = (int)(b[r] & 0xFFFFFFFFULL);
        const float4* on = (const float4*)(outputs + (size_t)nb * NCH);
        float4 n0 = on[0], n1 = on[1], n2 = on[2], n3 = on[3];
        float acc = 0.0f, dd;
        dd = a0.x - n0.x; acc = fmaf(dd, dd, acc);
        dd = a0.y - n0.y; acc = fmaf(dd, dd, acc);
        dd = a0.z - n0.z; acc = fmaf(dd, dd, acc);
        dd = a0.w - n0.w; acc = fmaf(dd, dd, acc);
        dd = a1.x - n1.x; acc = fmaf(dd, dd, acc);
        dd = a1.y - n1.y; acc = fmaf(dd, dd, acc);
        dd = a1.z - n1.z; acc = fmaf(dd, dd, acc);
        dd = a1.w - n1.w; acc = fmaf(dd, dd, acc);
        dd = a2.x - n2.x; acc = fmaf(dd, dd, acc);
        dd = a2.y - n2.y; acc = fmaf(dd, dd, acc);
        dd = a2.z - n2.z; acc = fmaf(dd, dd, acc);
        dd = a2.w - n2.w; acc = fmaf(dd, dd, acc);
        dd = a3.x - n3.x; acc = fmaf(dd, dd, acc);
        dd = a3.y - n3.y; acc = fmaf(dd, dd, acc);
        dd = a3.z - n3.z; acc = fmaf(dd, dd, acc);
        dd = a3.w - n3.w; acc = fmaf(dd, dd, acc);
        ssum += sqrtf(acc);
    }
    g_partial[i] = ssum;

    // fused final reduction: last block does a fixed-order sum
    __syncthreads();
    __shared__ bool is_last;
    if (threadIdx.x == 0) {
        __threadfence();
        unsigned tk = atomicAdd(&g_ticket, 1);
        is_last = (tk == K5_NBLK - 1);
    }
    __syncthreads();
    if (is_last) {
        __threadfence();
        float acc = 0.0f;
        for (int j = threadIdx.x; j < NPTS; j += K5_TPB) acc += g_partial[j];
        __shared__ float sm[K5_TPB];
        sm[threadIdx.x] = acc;
        __syncthreads();
        for (int st = K5_TPB / 2; st > 0; st >>= 1) {
            if (threadIdx.x < st) sm[threadIdx.x] += sm[threadIdx.x + st];
            __syncthreads();
        }
        if (threadIdx.x == 0) {
            out[0] = sm[0] / (float)(NPTS * KNN);
            g_ticket = 0;  // reset for next graph replay
        }
    }
}

extern "C" void kernel_launch(void* const* d_in, const int* in_sizes, int n_in,
                              void* d_out, int out_size) {
    const float*  outputs = (const float*)d_in[0];
    const float2* points  = (const float2*)d_in[1];
    float* out = (float*)d_out;

    init_kernel<<<1, 1024>>>(points);
    bin_kernel<<<NPTS / 256, 256>>>(points);
    prefix_kernel<<<1, 1024>>>();
    scatter_kernel<<<NPTS / 256, 256>>>(points);
    search_kernel<<<K5_NBLK, K5_TPB>>>(outputs, points, out);
}

// round 8
// speedup vs baseline: 2.4494x; 2.4494x over previous
#include <cuda_runtime.h>
#include <cstdint>

// GeometricLoss via spatial grid, R8:
//  K1 build (1 CTA): bbox -> smem bin count -> smem prefix scan -> scatter
//     into g_pts4 {x,y,pid,0} + g_cellinfo {start,count}.
//  K2 search: ONE WARP PER QUERY, lanes scan disk/ring cells in parallel,
//     lane-local top-6, exact warp merge, ring expansion with exact bound,
//     fused neighbor-norm epilogue + last-block reduction.
// Selection uses unique keys (d2_bits<<32)|pid -> order-independent, exact
// jax.lax.top_k semantics (low-index tie-break), deterministic output.

#define NPTS 8192
#define NCH 16
#define KNN 5
#define G 64
#define NCELL (G * G)
#define FULLM 0xFFFFFFFFu
typedef unsigned long long ull;
#define SENT 0xFFFFFFFFFFFFFFFFULL

__device__ float4 g_pts4[NPTS];       // {x, y, bitcast(pid), 0}
__device__ int2   g_cellinfo[NCELL];  // {start, count}
__device__ float  g_partial[NPTS];
__device__ unsigned g_ticket;
__device__ float g_minx, g_miny, g_invw, g_invh, g_cwmin;

// ======================= K1: build (single CTA) =======================
__global__ __launch_bounds__(1024, 1)
void build_kernel(const float2* __restrict__ pts) {
    __shared__ int   s_cnt[NCELL];    // 16 KB
    __shared__ int   s_start[NCELL];  // 16 KB
    __shared__ int   s_sum[1024];     // 4 KB
    __shared__ float s_red[128];
    __shared__ float s_minx, s_miny, s_invw, s_invh;

    const int tid = threadIdx.x;
    const int lane = tid & 31, warp = tid >> 5;

#pragma unroll
    for (int i = 0; i < NCELL / 1024; i++) s_cnt[tid + i * 1024] = 0;
    if (tid == 0) g_ticket = 0;

    // ---- bbox ----
    float2 loc[NPTS / 1024];
    float mnx = 1e30f, mxx = -1e30f, mny = 1e30f, mxy = -1e30f;
#pragma unroll
    for (int i = 0; i < NPTS / 1024; i++) {
        float2 p = pts[tid + i * 1024];
        loc[i] = p;
        mnx = fminf(mnx, p.x); mxx = fmaxf(mxx, p.x);
        mny = fminf(mny, p.y); mxy = fmaxf(mxy, p.y);
    }
#pragma unroll
    for (int off = 16; off > 0; off >>= 1) {
        mnx = fminf(mnx, __shfl_xor_sync(FULLM, mnx, off));
        mxx = fmaxf(mxx, __shfl_xor_sync(FULLM, mxx, off));
        mny = fminf(mny, __shfl_xor_sync(FULLM, mny, off));
        mxy = fmaxf(mxy, __shfl_xor_sync(FULLM, mxy, off));
    }
    if (lane == 0) {
        s_red[warp] = mnx; s_red[32 + warp] = mxx;
        s_red[64 + warp] = mny; s_red[96 + warp] = mxy;
    }
    __syncthreads();
    if (tid == 0) {
        for (int w = 1; w < 32; w++) {
            s_red[0]  = fminf(s_red[0],  s_red[w]);
            s_red[32] = fmaxf(s_red[32], s_red[32 + w]);
            s_red[64] = fminf(s_red[64], s_red[64 + w]);
            s_red[96] = fmaxf(s_red[96], s_red[96 + w]);
        }
        float w = s_red[32] - s_red[0], h = s_red[96] - s_red[64];
        s_minx = s_red[0];  g_minx = s_red[0];
        s_miny = s_red[64]; g_miny = s_red[64];
        float iw = (w > 0.0f) ? (float)G / w : 0.0f;
        float ih = (h > 0.0f) ? (float)G / h : 0.0f;
        s_invw = iw; g_invw = iw;
        s_invh = ih; g_invh = ih;
        g_cwmin = fminf(w / (float)G, h / (float)G);
    }
    __syncthreads();

    // ---- count ----
    int mycell[NPTS / 1024];
#pragma unroll
    for (int i = 0; i < NPTS / 1024; i++) {
        int cx = min(max((int)((loc[i].x - s_minx) * s_invw), 0), G - 1);
        int cy = min(max((int)((loc[i].y - s_miny) * s_invh), 0), G - 1);
        int c = cy * G + cx;
        mycell[i] = c;
        atomicAdd(&s_cnt[c], 1);
    }
    __syncthreads();

    // ---- prefix scan over 4096 counts (4 per thread + Hillis-Steele) ----
    int v[4], run = 0;
    const int base = tid * 4;
#pragma unroll
    for (int i = 0; i < 4; i++) { v[i] = run; run += s_cnt[base + i]; }
    s_sum[tid] = run;
    __syncthreads();
    for (int off = 1; off < 1024; off <<= 1) {
        int x = s_sum[tid];
        int y = (tid >= off) ? s_sum[tid - off] : 0;
        __syncthreads();
        s_sum[tid] = x + y;
        __syncthreads();
    }
    int prev = (tid > 0) ? s_sum[tid - 1] : 0;
#pragma unroll
    for (int i = 0; i < 4; i++) {
        int st = prev + v[i];
        s_start[base + i] = st;
        g_cellinfo[base + i] = make_int2(st, s_cnt[base + i]);
    }
    __syncthreads();

    // ---- scatter (atomic cursor on s_start; order-independent downstream) --
#pragma unroll
    for (int i = 0; i < NPTS / 1024; i++) {
        int slot = atomicAdd(&s_start[mycell[i]], 1);
        g_pts4[slot] = make_float4(loc[i].x, loc[i].y,
                                   __int_as_float(tid + i * 1024), 0.0f);
    }
}

// ======================= K2: search (warp per query) ===================
#define STPB 256
#define SWPB (STPB / 32)            // 8 warps/CTA
#define SNBLK (NPTS / SWPB)         // 1024 CTAs

__device__ __forceinline__ void scan_cell(int x, int y, float qx, float qy,
                                          float th, ull* b) {
    if ((unsigned)x >= G || (unsigned)y >= G) return;
    int2 ci = g_cellinfo[y * G + x];
    int e = ci.x + ci.y;
    for (int j = ci.x; j < e; j++) {
        float4 P = g_pts4[j];
        float dx = qx - P.x;
        float dy = qy - P.y;
        float d2 = fmaf(dx, dx, dy * dy);
        if (d2 <= th) {  // <= so boundary ties resolve exactly via key
            ull key = ((ull)__float_as_uint(d2) << 32) |
                      (unsigned)__float_as_int(P.z);
            if (key < b[5]) {
                b[5] = key;
#pragma unroll
                for (int t = 5; t > 0; t--) {
                    if (b[t] < b[t - 1]) {
                        ull tmp = b[t]; b[t] = b[t - 1]; b[t - 1] = tmp;
                    }
                }
            }
        }
    }
}

// Exact warp merge: fold previous global ranks (rk) into lane-local sorted
// lists, then 6 warp-min extraction rounds. Keys unique -> exact.
__device__ __forceinline__ void merge6(ull* b, ull& rk, float& th, int lane) {
    if (lane < 6 && rk != SENT && rk < b[5]) {
        b[5] = rk;
#pragma unroll
        for (int t = 5; t > 0; t--) {
            if (b[t] < b[t - 1]) { ull tmp = b[t]; b[t] = b[t - 1]; b[t - 1] = tmp; }
        }
    }
    ull newrk = SENT;
#pragma unroll
    for (int r = 0; r < 6; r++) {
        ull m = b[0];
#pragma unroll
        for (int off = 16; off > 0; off >>= 1) {
            ull o = __shfl_xor_sync(FULLM, m, off);
            if (o < m) m = o;
        }
        if (lane == r) newrk = m;
        if (b[0] == m && m != SENT) {
            b[0] = b[1]; b[1] = b[2]; b[2] = b[3];
            b[3] = b[4]; b[4] = b[5]; b[5] = SENT;
        }
    }
    rk = newrk;
    ull k5 = __shfl_sync(FULLM, rk, 5);
    th = (k5 == SENT) ? __int_as_float(0x7F800000)
                      : __uint_as_float((unsigned)(k5 >> 32));
}

__global__ __launch_bounds__(STPB)
void search_kernel(const float* __restrict__ outputs,
                   const float2* __restrict__ pts,
                   float* __restrict__ out) {
    const int i = blockIdx.x * SWPB + (threadIdx.x >> 5);  // query index
    const int lane = threadIdx.x & 31;

    const float2 q = pts[i];
    const float cw = g_cwmin;
    const int cx = min(max((int)((q.x - g_minx) * g_invw), 0), G - 1);
    const int cy = min(max((int)((q.y - g_miny) * g_invh), 0), G - 1);

    ull b[6];
#pragma unroll
    for (int t = 0; t < 6; t++) b[t] = SENT;
    ull rk = SENT;
    float th = __int_as_float(0x7F800000);

    // disk D=1: 9 cells, one per lane
    if (lane < 9) scan_cell(cx + lane % 3 - 1, cy + lane / 3 - 1, q.x, q.y, th, b);
    merge6(b, rk, th, lane);

    int D = 1;
    while (D < G) {
        float bnd = (float)D * cw;
        if (th <= bnd * bnd) break;   // unscanned rings >= D+1 -> dist >= D*cw
        const int d = D + 1;
        const int ncells = 8 * d;
        for (int tb = 0; tb < ncells; tb += 32) {
            int t = tb + lane;
            if (t < ncells) {
                int x, y;
                int rowspan = 2 * d + 1;
                if (t < 2 * rowspan) {
                    int row = t / rowspan, k = t % rowspan;
                    x = cx - d + k;
                    y = row ? cy + d : cy - d;
                } else {
                    int t2 = t - 2 * rowspan;
                    int colspan = 2 * d - 1;
                    int col = t2 / colspan, k = t2 % colspan;
                    x = col ? cx + d : cx - d;
                    y = cy - d + 1 + k;
                }
                scan_cell(x, y, q.x, q.y, th, b);
            }
        }
        merge6(b, rk, th, lane);
        D = d;
    }

    // epilogue: rank 0 = self (min key); lanes 1..5 own the neighbors
    {
        float s = 0.0f;
        if (lane >= 1 && lane <= KNN) {
            int nb = (int)(rk & 0xFFFFFFFFULL);
            const float4* oq = (const float4*)(outputs + (size_t)i * NCH);
            const float4* on = (const float4*)(outputs + (size_t)nb * NCH);
            float acc = 0.0f;
#pragma unroll
            for (int c = 0; c < NCH / 4; c++) {
                float4 a = oq[c];
                float4 bb = on[c];
                float d;
                d = a.x - bb.x; acc = fmaf(d, d, acc);
                d = a.y - bb.y; acc = fmaf(d, d, acc);
                d = a.z - bb.z; acc = fmaf(d, d, acc);
                d = a.w - bb.w; acc = fmaf(d, d, acc);
            }
            s = sqrtf(acc);
        }
#pragma unroll
        for (int off = 16; off > 0; off >>= 1)
            s += __shfl_xor_sync(FULLM, s, off);
        if (lane == 0) g_partial[i] = s;
    }

    // fused final reduction: last CTA does a fixed-order sum
    __syncthreads();
    __shared__ bool is_last;
    if (threadIdx.x == 0) {
        __threadfence();
        unsigned tk = atomicAdd(&g_ticket, 1);
        is_last = (tk == SNBLK - 1);
    }
    __syncthreads();
    if (is_last) {
        __threadfence();
        float acc = 0.0f;
        for (int j = threadIdx.x; j < NPTS; j += STPB) acc += g_partial[j];
        __shared__ float sm[STPB];
        sm[threadIdx.x] = acc;
        __syncthreads();
        for (int st = STPB / 2; st > 0; st >>= 1) {
            if (threadIdx.x < st) sm[threadIdx.x] += sm[threadIdx.x + st];
            __syncthreads();
        }
        if (threadIdx.x == 0) {
            out[0] = sm[0] / (float)(NPTS * KNN);
            g_ticket = 0;  // reset for next graph replay
        }
    }
}

extern "C" void kernel_launch(void* const* d_in, const int* in_sizes, int n_in,
                              void* d_out, int out_size) {
    const float*  outputs = (const float*)d_in[0];
    const float2* points  = (const float2*)d_in[1];
    float* out = (float*)d_out;

    build_kernel<<<1, 1024>>>(points);
    search_kernel<<<SNBLK, STPB>>>(outputs, points, out);
}